// round 4
// baseline (speedup 1.0000x reference)
#include <cuda_runtime.h>
#include <cuda_bf16.h>
#include <math.h>

#define FULLMASK 0xffffffffu

static const int N_ROI = 116;
static const int G     = 128;
static const int DEG   = 32;
static const int NN    = G * N_ROI;        // 14848 nodes
static const int EE    = G * N_ROI * DEG;  // 475136 edges
static const int EPG   = N_ROI * DEG;      // 3712 edges per graph
static const int HID   = 64;
static const int HC    = 256;
static const int MAXDEG = 192;

// ---------------- device scratch (allocation-free) ----------------
__device__ float g_h0[NN * HID];        // post-embed
__device__ float g_h1[NN * HID];        // post GINE+MLP+LN
__device__ float g_xl[NN * HC];
__device__ float g_xr[NN * HC];
__device__ float g_out[NN * HC];        // GAT layer output (raw, pre-BN)
__device__ int   g_nodelist[NN * MAXDEG];   // edge id per (node, slot)
__device__ int   g_srclist[NN * MAXDEG];    // src node per (node, slot)
__device__ int   g_deg[NN];
__device__ float g_csum[HC];
__device__ float g_csq[HC];

// ---------------- f32x2 packed-FMA helpers (Blackwell) ----------------
__device__ __forceinline__ unsigned long long pk2(float lo, float hi) {
    unsigned long long r;
    asm("mov.b64 %0, {%1, %2};" : "=l"(r) : "f"(lo), "f"(hi));
    return r;
}
__device__ __forceinline__ void ffma2(unsigned long long& d, unsigned long long a,
                                      unsigned long long b) {
    asm("fma.rn.f32x2 %0, %1, %2, %0;" : "+l"(d) : "l"(a), "l"(b));
}
__device__ __forceinline__ void unpk2(float& lo, float& hi, unsigned long long v) {
    asm("mov.b64 {%0, %1}, %2;" : "=f"(lo), "=f"(hi) : "l"(v));
}

// ---------------- adjacency build: warp per node, ordered ballot compaction ----
__global__ void build_adj_k(const int* __restrict__ srcA, const int* __restrict__ dst) {
    int gw = (blockIdx.x * blockDim.x + threadIdx.x) >> 5;
    if (gw >= NN) return;
    int lane = threadIdx.x & 31;
    int n = gw;
    int g = n / N_ROI;
    int ebase = g * EPG;
    int count = 0;
    int* out  = g_nodelist + n * MAXDEG;
    int* outs = g_srclist  + n * MAXDEG;
    for (int i = 0; i < EPG; i += 32) {
        int e = ebase + i + lane;
        int d = dst[e];
        unsigned m = __ballot_sync(FULLMASK, d == n);
        if (d == n) {
            int rank = __popc(m & ((1u << lane) - 1u));
            int pos = count + rank;
            if (pos < MAXDEG) {
                out[pos]  = e;
                outs[pos] = srcA[e];
            }
        }
        count += __popc(m);
    }
    if (lane == 0) g_deg[n] = min(count, MAXDEG);
}

// ---------------- node embed ----------------
__global__ void embed_k(const float* __restrict__ x, const int* __restrict__ node_group,
                        const float* __restrict__ gemb, const float* __restrict__ W,
                        const float* __restrict__ b) {
    int n = blockIdx.x;
    int t = threadIdx.x;   // 64
    __shared__ float sx[132];
    for (int i = t; i < 116; i += 64) sx[i] = x[n * 116 + i];
    if (t < 16) sx[116 + t] = gemb[node_group[n] * 16 + t];
    __syncthreads();
    float acc = b[t];
    #pragma unroll 4
    for (int r = 0; r < 132; r++) acc += sx[r] * W[r * 64 + t];
    g_h0[n * 64 + t] = acc >= 0.f ? acc : 0.01f * acc;
}

// ---------------- GINE aggregate + MLP + LayerNorm (chunked prefetch) ---------
__global__ void gine_k(const float* __restrict__ ea,
                       const float* __restrict__ We, const float* __restrict__ be,
                       const float* __restrict__ W1, const float* __restrict__ b1,
                       const float* __restrict__ W2, const float* __restrict__ b2,
                       const float* __restrict__ lng, const float* __restrict__ lnb) {
    int n = blockIdx.x;
    int t = threadIdx.x;   // 64
    __shared__ float sh[64], sh2[64], ws[2], wq[2];
    float s = g_h0[n * 64 + t];
    int d = g_deg[n];
    const int* lst = g_nodelist + n * MAXDEG;
    const int* sl  = g_srclist  + n * MAXDEG;
    float bec = be[t];
    float w0 = We[t], w1 = We[64 + t], w2 = We[128 + t], w3 = We[192 + t], w4 = We[256 + t];
    for (int i0 = 0; i0 < d; i0 += 4) {
        int cn = min(4, d - i0);
        float hv[4], em[4];
        #pragma unroll
        for (int j = 0; j < 4; j++) {
            if (j < cn) {
                int e = lst[i0 + j];
                int src = sl[i0 + j];
                hv[j] = g_h0[src * 64 + t];
                const float* a = ea + (long)e * 5;
                em[j] = bec + a[0] * w0 + a[1] * w1 + a[2] * w2 + a[3] * w3 + a[4] * w4;
            }
        }
        #pragma unroll
        for (int j = 0; j < 4; j++) {
            if (j < cn) {
                float m = em[j] >= 0.f ? em[j] : 0.01f * em[j];
                float v = hv[j] + m;
                s += v > 0.f ? v : 0.f;
            }
        }
    }
    sh[t] = s;
    __syncthreads();
    float acc = b1[t];
    #pragma unroll 8
    for (int r = 0; r < 64; r++) acc += sh[r] * W1[r * 64 + t];
    acc = acc >= 0.f ? acc : 0.01f * acc;
    sh2[t] = acc;
    __syncthreads();
    float acc2 = b2[t];
    #pragma unroll 8
    for (int r = 0; r < 64; r++) acc2 += sh2[r] * W2[r * 64 + t];
    acc2 = acc2 >= 0.f ? acc2 : 0.01f * acc2;
    float su = acc2, sq = acc2 * acc2;
    for (int o = 16; o; o >>= 1) {
        su += __shfl_down_sync(FULLMASK, su, o);
        sq += __shfl_down_sync(FULLMASK, sq, o);
    }
    if ((t & 31) == 0) { ws[t >> 5] = su; wq[t >> 5] = sq; }
    __syncthreads();
    float mu  = (ws[0] + ws[1]) * (1.f / 64.f);
    float var = (wq[0] + wq[1]) * (1.f / 64.f) - mu * mu;
    g_h1[n * 64 + t] = (acc2 - mu) * rsqrtf(var + 1e-5f) * lng[t] + lnb[t];
}

// ---------------- xlxr layer 0: scalar (near FMA floor already) ----------------
__global__ void xlxr0_k(const float* __restrict__ Wl, const float* __restrict__ Wr) {
    int nb = blockIdx.x * 16;
    int t = threadIdx.x;   // 256
    __shared__ float sh[16][HID];
    for (int i = t; i < 16 * 64; i += 256) {
        int j = i >> 6, c = i & 63;
        sh[j][c] = g_h1[(nb + j) * 64 + c];
    }
    __syncthreads();
    float al[16], ar[16];
    #pragma unroll
    for (int j = 0; j < 16; j++) { al[j] = 0.f; ar[j] = 0.f; }
    for (int r = 0; r < 64; r++) {
        float wl = Wl[r * 256 + t], wr = Wr[r * 256 + t];
        #pragma unroll
        for (int j = 0; j < 16; j++) {
            float hv = sh[j][r];
            al[j] += hv * wl;
            ar[j] += hv * wr;
        }
    }
    #pragma unroll
    for (int j = 0; j < 16; j++) {
        g_xl[(nb + j) * 256 + t] = al[j];
        g_xr[(nb + j) * 256 + t] = ar[j];
    }
}

// ---------------- xlxr layer 1: f32x2 packed FMA, BN of layer 0 fused in ------
__global__ void xlxr1_k(const float* __restrict__ Wl, const float* __restrict__ Wr,
                        const float* __restrict__ bng, const float* __restrict__ bnb) {
    int nb = blockIdx.x * 16;
    int t = threadIdx.x;   // 256
    __shared__ unsigned long long sh2[16][HC];   // h duplicated into both f32x2 lanes
    for (int i = t; i < 16 * 256; i += 256) {
        int j = i >> 8, c = i & 255;
        float mu  = g_csum[c] * (1.f / NN);
        float var = g_csq[c] * (1.f / NN) - mu * mu;
        float v = g_out[(nb + j) * 256 + c];
        v = (v - mu) * rsqrtf(var + 1e-5f) * bng[c] + bnb[c];
        v = v >= 0.f ? v : 0.01f * v;
        sh2[j][c] = pk2(v, v);
    }
    __syncthreads();
    unsigned long long acc[16];
    #pragma unroll
    for (int j = 0; j < 16; j++) acc[j] = 0ull;
    #pragma unroll 4
    for (int r = 0; r < 256; r++) {
        unsigned long long w2 = pk2(Wl[r * 256 + t], Wr[r * 256 + t]);
        #pragma unroll
        for (int j = 0; j < 16; j++) ffma2(acc[j], sh2[j][r], w2);
    }
    #pragma unroll
    for (int j = 0; j < 16; j++) {
        float lo, hi;
        unpk2(lo, hi, acc[j]);
        g_xl[(nb + j) * 256 + t] = lo;
        g_xr[(nb + j) * 256 + t] = hi;
    }
}

// ---------------- fused GATv2: single-pass online softmax ----------------------
// Block per node, 256 threads = 4 heads x 64 channels. Each edge's xl row is
// gathered ONCE and folded into a running (max, sum, acc) per channel.
__global__ void gat_fused_k(const float* __restrict__ ea,
                            const float* __restrict__ WeP,   // [5,256]
                            const float* __restrict__ attF)  // [4*64]
{
    int n = blockIdx.x;
    int t = threadIdx.x;     // 256; h = t>>6, c = t&63, channel = t
    int lane = t & 31, wid = t >> 5;
    int h = t >> 6;
    float w0 = WeP[t], w1 = WeP[256 + t], w2 = WeP[512 + t],
          w3 = WeP[768 + t], w4 = WeP[1024 + t];
    float av  = attF[t];
    float xrv = g_xr[n * 256 + t];
    int d = g_deg[n];
    const int* lst = g_nodelist + n * MAXDEG;
    const int* sl  = g_srclist  + n * MAXDEG;
    __shared__ float red[2][4][8];   // [buf][chunk-slot][warp]
    float m = -1e30f, ssum = 0.f, acc = 0.f;
    int buf = 0;
    for (int i0 = 0; i0 < d; i0 += 4, buf ^= 1) {
        int cn = min(4, d - i0);
        float xlv[4], ep[4];
        #pragma unroll
        for (int j = 0; j < 4; j++) {
            if (j < cn) {
                int e = lst[i0 + j];
                int s = sl[i0 + j];
                xlv[j] = g_xl[s * 256 + t];          // 4 independent gathers in flight
                const float* a = ea + (long)e * 5;
                ep[j] = a[0] * w0 + a[1] * w1 + a[2] * w2 + a[3] * w3 + a[4] * w4;
            }
        }
        #pragma unroll
        for (int j = 0; j < 4; j++) {
            if (j < cn) {
                float z = xlv[j] + xrv + ep[j];
                z = z >= 0.f ? z : 0.2f * z;          // GATv2 leaky 0.2
                float p = z * av;
                #pragma unroll
                for (int o = 16; o; o >>= 1) p += __shfl_xor_sync(FULLMASK, p, o);
                if (lane == 0) red[buf][j][wid] = p;
            }
        }
        __syncthreads();
        #pragma unroll
        for (int j = 0; j < 4; j++) {
            if (j < cn) {
                float v = red[buf][j][2 * h] + red[buf][j][2 * h + 1];
                float nm = fmaxf(m, v);
                float f   = __expf(m - nm);
                float wgt = __expf(v - nm);
                ssum = ssum * f + wgt;
                acc  = acc  * f + wgt * xlv[j];
                m = nm;
            }
        }
    }
    g_out[n * 256 + t] = acc / (ssum + 1e-16f);   // bias absorbed by BatchNorm
}

// ---------------- BatchNorm statistics ----------------
__global__ void zero_stats_k() {
    int t = threadIdx.x;
    g_csum[t] = 0.f;
    g_csq[t]  = 0.f;
}

__global__ void bnstat_k() {
    int t = threadIdx.x;  // 256 = channel
    int rows = (NN + gridDim.x - 1) / gridDim.x;
    int r0 = blockIdx.x * rows;
    int r1 = min(NN, r0 + rows);
    float s = 0.f, q = 0.f;
    for (int r = r0; r < r1; r++) {
        float v = g_out[r * 256 + t];
        s += v;
        q += v * v;
    }
    atomicAdd(&g_csum[t], s);
    atomicAdd(&g_csq[t], q);
}

// ---------------- pool + classifier (BN+leaky of layer 1 fused in) -------------
__global__ void pool_k(const float* __restrict__ W, const float* __restrict__ bb,
                       const float* __restrict__ gam, const float* __restrict__ bet,
                       float* __restrict__ outp) {
    int g = blockIdx.x;   // 128 graphs
    int t = threadIdx.x;  // 256 = channel
    float mu  = g_csum[t] * (1.f / NN);
    float var = g_csq[t] * (1.f / NN) - mu * mu;
    float rs = rsqrtf(var + 1e-5f) * gam[t];
    float bt = bet[t];
    float s = 0.f;
    int base = g * N_ROI;
    for (int r = 0; r < N_ROI; r++) {
        float v = g_out[(base + r) * 256 + t];
        v = (v - mu) * rs + bt;
        v = v >= 0.f ? v : 0.01f * v;
        s += v;
    }
    s *= (1.f / (float)N_ROI);
    float c0 = s * W[t * 2], c1 = s * W[t * 2 + 1];
    __shared__ float r0s[8], r1s[8];
    for (int o = 16; o; o >>= 1) {
        c0 += __shfl_down_sync(FULLMASK, c0, o);
        c1 += __shfl_down_sync(FULLMASK, c1, o);
    }
    if ((t & 31) == 0) { r0s[t >> 5] = c0; r1s[t >> 5] = c1; }
    __syncthreads();
    if (t == 0) {
        float a = 0.f, b2 = 0.f;
        for (int i = 0; i < 8; i++) { a += r0s[i]; b2 += r1s[i]; }
        outp[g * 2]     = a  + bb[0];
        outp[g * 2 + 1] = b2 + bb[1];
    }
}

// ---------------- launch --------------------------------------------------------
extern "C" void kernel_launch(void* const* d_in, const int* in_sizes, int n_in,
                              void* d_out, int out_size) {
    const float* x          = (const float*)d_in[0];
    const int*   edge_index = (const int*)  d_in[1];
    const float* edge_attr  = (const float*)d_in[2];
    const int*   node_group = (const int*)  d_in[4];
    const float* group_emb  = (const float*)d_in[5];
    const float* W_embed    = (const float*)d_in[6];
    const float* b_embed    = (const float*)d_in[7];
    const float* We_enc     = (const float*)d_in[8];
    const float* be_enc     = (const float*)d_in[9];
    const float* W1         = (const float*)d_in[10];
    const float* b1         = (const float*)d_in[11];
    const float* W2         = (const float*)d_in[12];
    const float* b2         = (const float*)d_in[13];
    const float* ln_g       = (const float*)d_in[14];
    const float* ln_b       = (const float*)d_in[15];
    const float* l0_Wl      = (const float*)d_in[16];
    const float* l0_Wr      = (const float*)d_in[17];
    const float* l0_We      = (const float*)d_in[18];
    const float* l0_att     = (const float*)d_in[19];
    const float* l0_bn_g    = (const float*)d_in[21];
    const float* l0_bn_b    = (const float*)d_in[22];
    const float* l1_Wl      = (const float*)d_in[23];
    const float* l1_Wr      = (const float*)d_in[24];
    const float* l1_We      = (const float*)d_in[25];
    const float* l1_att     = (const float*)d_in[26];
    const float* l1_bn_g    = (const float*)d_in[28];
    const float* l1_bn_b    = (const float*)d_in[29];
    const float* fc2_W      = (const float*)d_in[30];
    const float* fc2_b      = (const float*)d_in[31];

    const int* srcp = edge_index;
    const int* dstp = edge_index + EE;

    build_adj_k<<<(NN * 32 + 255) / 256, 256>>>(srcp, dstp);
    embed_k<<<NN, 64>>>(x, node_group, group_emb, W_embed, b_embed);
    gine_k<<<NN, 64>>>(edge_attr, We_enc, be_enc, W1, b1, W2, b2, ln_g, ln_b);

    // GAT layer 0
    xlxr0_k<<<NN / 16, 256>>>(l0_Wl, l0_Wr);
    gat_fused_k<<<NN, 256>>>(edge_attr, l0_We, l0_att);
    zero_stats_k<<<1, 256>>>();
    bnstat_k<<<256, 256>>>();

    // GAT layer 1 (BN of layer 0 fused into xlxr1 input load)
    xlxr1_k<<<NN / 16, 256>>>(l1_Wl, l1_Wr, l0_bn_g, l0_bn_b);
    gat_fused_k<<<NN, 256>>>(edge_attr, l1_We, l1_att);
    zero_stats_k<<<1, 256>>>();
    bnstat_k<<<256, 256>>>();

    // pool + classifier (BN of layer 1 fused in)
    pool_k<<<G, 256>>>(fc2_W, fc2_b, l1_bn_g, l1_bn_b, (float*)d_out);
}

// round 5
// speedup vs baseline: 1.2787x; 1.2787x over previous
#include <cuda_runtime.h>
#include <cuda_bf16.h>
#include <math.h>

#define FULLMASK 0xffffffffu

static const int N_ROI = 116;
static const int G     = 128;
static const int DEG   = 32;
static const int NN    = G * N_ROI;        // 14848 nodes
static const int EE    = G * N_ROI * DEG;  // 475136 edges
static const int EPG   = N_ROI * DEG;      // 3712 edges per graph
static const int HID   = 64;
static const int HC    = 256;
static const int MAXDEG = 192;

// ---------------- device scratch (allocation-free) ----------------
__device__ float g_h0[NN * HID];        // post-embed
__device__ float g_h1[NN * HID];        // post GINE+MLP+LN
__device__ float g_xl[NN * HC];
__device__ float g_xr[NN * HC];
__device__ float g_out[NN * HC];        // GAT layer output (raw, pre-BN)
__device__ int   g_nodelist[NN * MAXDEG];   // edge id per (node, slot)
__device__ int   g_srclist[NN * MAXDEG];    // src node per (node, slot)
__device__ int   g_deg[NN];
__device__ float g_csum[HC];
__device__ float g_csq[HC];

// ---------------- f32x2 packed-FMA helpers (Blackwell) ----------------
__device__ __forceinline__ unsigned long long pk2(float lo, float hi) {
    unsigned long long r;
    asm("mov.b64 %0, {%1, %2};" : "=l"(r) : "f"(lo), "f"(hi));
    return r;
}
__device__ __forceinline__ void ffma2(unsigned long long& d, unsigned long long a,
                                      unsigned long long b) {
    asm("fma.rn.f32x2 %0, %1, %2, %0;" : "+l"(d) : "l"(a), "l"(b));
}
__device__ __forceinline__ void unpk2(float& lo, float& hi, unsigned long long v) {
    asm("mov.b64 {%0, %1}, %2;" : "=f"(lo), "=f"(hi) : "l"(v));
}

// ---------------- adjacency build: warp per node, ordered ballot compaction ----
__global__ void build_adj_k(const int* __restrict__ srcA, const int* __restrict__ dst) {
    int gw = (blockIdx.x * blockDim.x + threadIdx.x) >> 5;
    if (gw >= NN) return;
    int lane = threadIdx.x & 31;
    int n = gw;
    int g = n / N_ROI;
    int ebase = g * EPG;
    int count = 0;
    int* out  = g_nodelist + n * MAXDEG;
    int* outs = g_srclist  + n * MAXDEG;
    for (int i = 0; i < EPG; i += 32) {
        int e = ebase + i + lane;
        int d = dst[e];
        unsigned m = __ballot_sync(FULLMASK, d == n);
        if (d == n) {
            int rank = __popc(m & ((1u << lane) - 1u));
            int pos = count + rank;
            if (pos < MAXDEG) {
                out[pos]  = e;
                outs[pos] = srcA[e];
            }
        }
        count += __popc(m);
    }
    if (lane == 0) g_deg[n] = min(count, MAXDEG);
}

// ---------------- node embed ----------------
__global__ void embed_k(const float* __restrict__ x, const int* __restrict__ node_group,
                        const float* __restrict__ gemb, const float* __restrict__ W,
                        const float* __restrict__ b) {
    int n = blockIdx.x;
    int t = threadIdx.x;   // 64
    __shared__ float sx[132];
    for (int i = t; i < 116; i += 64) sx[i] = x[n * 116 + i];
    if (t < 16) sx[116 + t] = gemb[node_group[n] * 16 + t];
    __syncthreads();
    float acc = b[t];
    #pragma unroll 4
    for (int r = 0; r < 132; r++) acc += sx[r] * W[r * 64 + t];
    g_h0[n * 64 + t] = acc >= 0.f ? acc : 0.01f * acc;
}

// ---------------- GINE aggregate + MLP + LayerNorm (chunked prefetch) ---------
__global__ void gine_k(const float* __restrict__ ea,
                       const float* __restrict__ We, const float* __restrict__ be,
                       const float* __restrict__ W1, const float* __restrict__ b1,
                       const float* __restrict__ W2, const float* __restrict__ b2,
                       const float* __restrict__ lng, const float* __restrict__ lnb) {
    int n = blockIdx.x;
    int t = threadIdx.x;   // 64
    __shared__ float sh[64], sh2[64], ws[2], wq[2];
    float s = g_h0[n * 64 + t];
    int d = g_deg[n];
    const int* lst = g_nodelist + n * MAXDEG;
    const int* sl  = g_srclist  + n * MAXDEG;
    float bec = be[t];
    float w0 = We[t], w1 = We[64 + t], w2 = We[128 + t], w3 = We[192 + t], w4 = We[256 + t];
    for (int i0 = 0; i0 < d; i0 += 4) {
        int cn = min(4, d - i0);
        float hv[4], em[4];
        #pragma unroll
        for (int j = 0; j < 4; j++) {
            if (j < cn) {
                int e = lst[i0 + j];
                int src = sl[i0 + j];
                hv[j] = g_h0[src * 64 + t];
                const float* a = ea + (long)e * 5;
                em[j] = bec + a[0] * w0 + a[1] * w1 + a[2] * w2 + a[3] * w3 + a[4] * w4;
            }
        }
        #pragma unroll
        for (int j = 0; j < 4; j++) {
            if (j < cn) {
                float m = em[j] >= 0.f ? em[j] : 0.01f * em[j];
                float v = hv[j] + m;
                s += v > 0.f ? v : 0.f;
            }
        }
    }
    sh[t] = s;
    __syncthreads();
    float acc = b1[t];
    #pragma unroll 8
    for (int r = 0; r < 64; r++) acc += sh[r] * W1[r * 64 + t];
    acc = acc >= 0.f ? acc : 0.01f * acc;
    sh2[t] = acc;
    __syncthreads();
    float acc2 = b2[t];
    #pragma unroll 8
    for (int r = 0; r < 64; r++) acc2 += sh2[r] * W2[r * 64 + t];
    acc2 = acc2 >= 0.f ? acc2 : 0.01f * acc2;
    float su = acc2, sq = acc2 * acc2;
    for (int o = 16; o; o >>= 1) {
        su += __shfl_down_sync(FULLMASK, su, o);
        sq += __shfl_down_sync(FULLMASK, sq, o);
    }
    if ((t & 31) == 0) { ws[t >> 5] = su; wq[t >> 5] = sq; }
    __syncthreads();
    float mu  = (ws[0] + ws[1]) * (1.f / 64.f);
    float var = (wq[0] + wq[1]) * (1.f / 64.f) - mu * mu;
    g_h1[n * 64 + t] = (acc2 - mu) * rsqrtf(var + 1e-5f) * lng[t] + lnb[t];
}

// ---------------- xlxr layer 0: scalar (near FMA floor already) ----------------
__global__ void xlxr0_k(const float* __restrict__ Wl, const float* __restrict__ Wr) {
    int nb = blockIdx.x * 16;
    int t = threadIdx.x;   // 256
    __shared__ float sh[16][HID];
    for (int i = t; i < 16 * 64; i += 256) {
        int j = i >> 6, c = i & 63;
        sh[j][c] = g_h1[(nb + j) * 64 + c];
    }
    __syncthreads();
    float al[16], ar[16];
    #pragma unroll
    for (int j = 0; j < 16; j++) { al[j] = 0.f; ar[j] = 0.f; }
    for (int r = 0; r < 64; r++) {
        float wl = Wl[r * 256 + t], wr = Wr[r * 256 + t];
        #pragma unroll
        for (int j = 0; j < 16; j++) {
            float hv = sh[j][r];
            al[j] += hv * wl;
            ar[j] += hv * wr;
        }
    }
    #pragma unroll
    for (int j = 0; j < 16; j++) {
        g_xl[(nb + j) * 256 + t] = al[j];
        g_xr[(nb + j) * 256 + t] = ar[j];
    }
}

// ---------------- xlxr layer 1: f32x2 packed FMA, BN of layer 0 fused in ------
__global__ void xlxr1_k(const float* __restrict__ Wl, const float* __restrict__ Wr,
                        const float* __restrict__ bng, const float* __restrict__ bnb) {
    int nb = blockIdx.x * 16;
    int t = threadIdx.x;   // 256
    __shared__ unsigned long long sh2[16][HC];   // h duplicated into both f32x2 lanes
    for (int i = t; i < 16 * 256; i += 256) {
        int j = i >> 8, c = i & 255;
        float mu  = g_csum[c] * (1.f / NN);
        float var = g_csq[c] * (1.f / NN) - mu * mu;
        float v = g_out[(nb + j) * 256 + c];
        v = (v - mu) * rsqrtf(var + 1e-5f) * bng[c] + bnb[c];
        v = v >= 0.f ? v : 0.01f * v;
        sh2[j][c] = pk2(v, v);
    }
    __syncthreads();
    unsigned long long acc[16];
    #pragma unroll
    for (int j = 0; j < 16; j++) acc[j] = 0ull;
    #pragma unroll 4
    for (int r = 0; r < 256; r++) {
        unsigned long long w2 = pk2(Wl[r * 256 + t], Wr[r * 256 + t]);
        #pragma unroll
        for (int j = 0; j < 16; j++) ffma2(acc[j], sh2[j][r], w2);
    }
    #pragma unroll
    for (int j = 0; j < 16; j++) {
        float lo, hi;
        unpk2(lo, hi, acc[j]);
        g_xl[(nb + j) * 256 + t] = lo;
        g_xr[(nb + j) * 256 + t] = hi;
    }
}

// ---------------- GATv2: warp per (node, head), barrier-free online softmax ----
// Block = 256 threads = 8 warps = 2 nodes x 4 heads. Lane owns channels
// (lane, lane+32) of its head. Logit reduce = 5-step shuffle butterfly.
__global__ void gat_warp_k(const float* __restrict__ ea,
                           const float* __restrict__ WeP,   // [5,256]
                           const float* __restrict__ attF)  // [4*64]
{
    int t = threadIdx.x, lane = t & 31, wid = t >> 5;
    int n = blockIdx.x * 2 + (wid >> 2);
    int h = wid & 3;
    int base = h * 64 + lane;
    float wp0 = WeP[base],        wp1 = WeP[256 + base],  wp2 = WeP[512 + base],
          wp3 = WeP[768 + base],  wp4 = WeP[1024 + base];
    float wq0 = WeP[base + 32],       wq1 = WeP[256 + base + 32], wq2 = WeP[512 + base + 32],
          wq3 = WeP[768 + base + 32], wq4 = WeP[1024 + base + 32];
    float a1 = attF[base], a2 = attF[base + 32];
    float xr1 = g_xr[n * 256 + base], xr2 = g_xr[n * 256 + base + 32];
    int d = g_deg[n];
    const int* lst = g_nodelist + n * MAXDEG;
    const int* sl  = g_srclist  + n * MAXDEG;
    float m = -1e30f, ssum = 0.f, acc1 = 0.f, acc2 = 0.f;
    int i = 0;
    for (; i + 2 <= d; i += 2) {
        int e0 = lst[i], e1 = lst[i + 1];
        int s0 = sl[i],  s1 = sl[i + 1];
        float x10 = g_xl[s0 * 256 + base], x20 = g_xl[s0 * 256 + base + 32];
        float x11 = g_xl[s1 * 256 + base], x21 = g_xl[s1 * 256 + base + 32];
        const float* A0 = ea + (long)e0 * 5;
        const float* A1 = ea + (long)e1 * 5;
        float b00 = A0[0], b01 = A0[1], b02 = A0[2], b03 = A0[3], b04 = A0[4];
        float b10 = A1[0], b11 = A1[1], b12 = A1[2], b13 = A1[3], b14 = A1[4];
        float ep10 = b00 * wp0 + b01 * wp1 + b02 * wp2 + b03 * wp3 + b04 * wp4;
        float ep20 = b00 * wq0 + b01 * wq1 + b02 * wq2 + b03 * wq3 + b04 * wq4;
        float ep11 = b10 * wp0 + b11 * wp1 + b12 * wp2 + b13 * wp3 + b14 * wp4;
        float ep21 = b10 * wq0 + b11 * wq1 + b12 * wq2 + b13 * wq3 + b14 * wq4;
        float z10 = x10 + xr1 + ep10; z10 = z10 >= 0.f ? z10 : 0.2f * z10;
        float z20 = x20 + xr2 + ep20; z20 = z20 >= 0.f ? z20 : 0.2f * z20;
        float z11 = x11 + xr1 + ep11; z11 = z11 >= 0.f ? z11 : 0.2f * z11;
        float z21 = x21 + xr2 + ep21; z21 = z21 >= 0.f ? z21 : 0.2f * z21;
        float p0 = z10 * a1 + z20 * a2;
        float p1 = z11 * a1 + z21 * a2;
        #pragma unroll
        for (int o = 16; o; o >>= 1) {
            p0 += __shfl_xor_sync(FULLMASK, p0, o);
            p1 += __shfl_xor_sync(FULLMASK, p1, o);
        }
        // online update, edge 0 then edge 1
        {
            float nm = fmaxf(m, p0);
            float f = __expf(m - nm), w = __expf(p0 - nm);
            ssum = ssum * f + w;
            acc1 = acc1 * f + w * x10;
            acc2 = acc2 * f + w * x20;
            m = nm;
        }
        {
            float nm = fmaxf(m, p1);
            float f = __expf(m - nm), w = __expf(p1 - nm);
            ssum = ssum * f + w;
            acc1 = acc1 * f + w * x11;
            acc2 = acc2 * f + w * x21;
            m = nm;
        }
    }
    if (i < d) {
        int e0 = lst[i], s0 = sl[i];
        float x10 = g_xl[s0 * 256 + base], x20 = g_xl[s0 * 256 + base + 32];
        const float* A0 = ea + (long)e0 * 5;
        float b00 = A0[0], b01 = A0[1], b02 = A0[2], b03 = A0[3], b04 = A0[4];
        float ep10 = b00 * wp0 + b01 * wp1 + b02 * wp2 + b03 * wp3 + b04 * wp4;
        float ep20 = b00 * wq0 + b01 * wq1 + b02 * wq2 + b03 * wq3 + b04 * wq4;
        float z10 = x10 + xr1 + ep10; z10 = z10 >= 0.f ? z10 : 0.2f * z10;
        float z20 = x20 + xr2 + ep20; z20 = z20 >= 0.f ? z20 : 0.2f * z20;
        float p0 = z10 * a1 + z20 * a2;
        #pragma unroll
        for (int o = 16; o; o >>= 1) p0 += __shfl_xor_sync(FULLMASK, p0, o);
        float nm = fmaxf(m, p0);
        float f = __expf(m - nm), w = __expf(p0 - nm);
        ssum = ssum * f + w;
        acc1 = acc1 * f + w * x10;
        acc2 = acc2 * f + w * x20;
        m = nm;
    }
    float inv = 1.f / (ssum + 1e-16f);
    g_out[n * 256 + base]      = acc1 * inv;   // bias absorbed by BatchNorm
    g_out[n * 256 + base + 32] = acc2 * inv;
}

// ---------------- BatchNorm statistics ----------------
__global__ void zero_stats_k() {
    int t = threadIdx.x;
    g_csum[t] = 0.f;
    g_csq[t]  = 0.f;
}

__global__ void bnstat_k() {
    int t = threadIdx.x;  // 256 = channel
    int rows = (NN + gridDim.x - 1) / gridDim.x;
    int r0 = blockIdx.x * rows;
    int r1 = min(NN, r0 + rows);
    float s = 0.f, q = 0.f;
    for (int r = r0; r < r1; r++) {
        float v = g_out[r * 256 + t];
        s += v;
        q += v * v;
    }
    atomicAdd(&g_csum[t], s);
    atomicAdd(&g_csq[t], q);
}

// ---------------- pool + classifier (BN+leaky of layer 1 fused in) -------------
__global__ void pool_k(const float* __restrict__ W, const float* __restrict__ bb,
                       const float* __restrict__ gam, const float* __restrict__ bet,
                       float* __restrict__ outp) {
    int g = blockIdx.x;   // 128 graphs
    int t = threadIdx.x;  // 256 = channel
    float mu  = g_csum[t] * (1.f / NN);
    float var = g_csq[t] * (1.f / NN) - mu * mu;
    float rs = rsqrtf(var + 1e-5f) * gam[t];
    float bt = bet[t];
    float s = 0.f;
    int base = g * N_ROI;
    for (int r = 0; r < N_ROI; r++) {
        float v = g_out[(base + r) * 256 + t];
        v = (v - mu) * rs + bt;
        v = v >= 0.f ? v : 0.01f * v;
        s += v;
    }
    s *= (1.f / (float)N_ROI);
    float c0 = s * W[t * 2], c1 = s * W[t * 2 + 1];
    __shared__ float r0s[8], r1s[8];
    for (int o = 16; o; o >>= 1) {
        c0 += __shfl_down_sync(FULLMASK, c0, o);
        c1 += __shfl_down_sync(FULLMASK, c1, o);
    }
    if ((t & 31) == 0) { r0s[t >> 5] = c0; r1s[t >> 5] = c1; }
    __syncthreads();
    if (t == 0) {
        float a = 0.f, b2 = 0.f;
        for (int i = 0; i < 8; i++) { a += r0s[i]; b2 += r1s[i]; }
        outp[g * 2]     = a  + bb[0];
        outp[g * 2 + 1] = b2 + bb[1];
    }
}

// ---------------- launch --------------------------------------------------------
extern "C" void kernel_launch(void* const* d_in, const int* in_sizes, int n_in,
                              void* d_out, int out_size) {
    const float* x          = (const float*)d_in[0];
    const int*   edge_index = (const int*)  d_in[1];
    const float* edge_attr  = (const float*)d_in[2];
    const int*   node_group = (const int*)  d_in[4];
    const float* group_emb  = (const float*)d_in[5];
    const float* W_embed    = (const float*)d_in[6];
    const float* b_embed    = (const float*)d_in[7];
    const float* We_enc     = (const float*)d_in[8];
    const float* be_enc     = (const float*)d_in[9];
    const float* W1         = (const float*)d_in[10];
    const float* b1         = (const float*)d_in[11];
    const float* W2         = (const float*)d_in[12];
    const float* b2         = (const float*)d_in[13];
    const float* ln_g       = (const float*)d_in[14];
    const float* ln_b       = (const float*)d_in[15];
    const float* l0_Wl      = (const float*)d_in[16];
    const float* l0_Wr      = (const float*)d_in[17];
    const float* l0_We      = (const float*)d_in[18];
    const float* l0_att     = (const float*)d_in[19];
    const float* l0_bn_g    = (const float*)d_in[21];
    const float* l0_bn_b    = (const float*)d_in[22];
    const float* l1_Wl      = (const float*)d_in[23];
    const float* l1_Wr      = (const float*)d_in[24];
    const float* l1_We      = (const float*)d_in[25];
    const float* l1_att     = (const float*)d_in[26];
    const float* l1_bn_g    = (const float*)d_in[28];
    const float* l1_bn_b    = (const float*)d_in[29];
    const float* fc2_W      = (const float*)d_in[30];
    const float* fc2_b      = (const float*)d_in[31];

    const int* srcp = edge_index;
    const int* dstp = edge_index + EE;

    build_adj_k<<<(NN * 32 + 255) / 256, 256>>>(srcp, dstp);
    embed_k<<<NN, 64>>>(x, node_group, group_emb, W_embed, b_embed);
    gine_k<<<NN, 64>>>(edge_attr, We_enc, be_enc, W1, b1, W2, b2, ln_g, ln_b);

    // GAT layer 0
    xlxr0_k<<<NN / 16, 256>>>(l0_Wl, l0_Wr);
    gat_warp_k<<<NN / 2, 256>>>(edge_attr, l0_We, l0_att);
    zero_stats_k<<<1, 256>>>();
    bnstat_k<<<256, 256>>>();

    // GAT layer 1 (BN of layer 0 fused into xlxr1 input load)
    xlxr1_k<<<NN / 16, 256>>>(l1_Wl, l1_Wr, l0_bn_g, l0_bn_b);
    gat_warp_k<<<NN / 2, 256>>>(edge_attr, l1_We, l1_att);
    zero_stats_k<<<1, 256>>>();
    bnstat_k<<<256, 256>>>();

    // pool + classifier (BN of layer 1 fused in)
    pool_k<<<G, 256>>>(fc2_W, fc2_b, l1_bn_g, l1_bn_b, (float*)d_out);
}